// round 10
// baseline (speedup 1.0000x reference)
#include <cuda_runtime.h>

// Problem constants (fixed: B_SZ=2, SEQ=4096, D=4096, R=8, U=4)
#define D_DIM  4096
#define D4     1024          // float4 per row
#define R_DIM  8
#define U_DIM  4
#define N_ROWS 8192

#define SPLITK 4
#define KQ4    (D4 / SPLITK) // 256 float4 per k-slice
#define NKT    (KQ4 / 32)    // 8 k-tiles per slice

// Split-k partials for t: 4 x 8192 x 8 floats = 1 MB (static, allowed).
__device__ float g_tp[SPLITK][N_ROWS * R_DIM];

// Packed f32x2 FMA: d = a*b + d (two fp32 lanes per instruction)
__device__ __forceinline__ void fma_f32x2(unsigned long long& d,
                                          unsigned long long a,
                                          unsigned long long b)
{
    asm("fma.rn.f32x2 %0, %1, %2, %0;" : "+l"(d) : "l"(a), "l"(b));
}

// ======================= Phase 1: partial t over one k-slice ================
// Warp owns 4 rows, lanes split k. Software-pipelined: tile kt+1's x loads
// are issued BEFORE tile kt's FMAs, keeping 8 LDG.128 (4 KB) per warp in
// flight at all times instead of 2 KB at 50% duty (the R9 latency limiter).
#define P1_THREADS 256
#define RPW 4                // rows per warp
#define P1_ROWS_PER_BLOCK (RPW * (P1_THREADS / 32))   // 32

__global__ __launch_bounds__(P1_THREADS)
void phase1_kernel(const float* __restrict__ x,
                   const float* __restrict__ B)
{
    const int tid  = threadIdx.x;
    const int w    = tid >> 5;
    const int lane = tid & 31;
    const int row0 = blockIdx.x * P1_ROWS_PER_BLOCK + w * RPW;
    const int kq   = blockIdx.y;
    const int kb4  = kq * KQ4;

    const ulonglong2* __restrict__ x2 = reinterpret_cast<const ulonglong2*>(x);
    const ulonglong2* __restrict__ B2 = reinterpret_cast<const ulonglong2*>(B);

    unsigned long long acc2[RPW][R_DIM];     // f32x2 accumulators
    #pragma unroll
    for (int a = 0; a < RPW; a++)
        #pragma unroll
        for (int r = 0; r < R_DIM; r++) acc2[a][r] = 0ull;

    // prologue: load tile 0
    ulonglong2 cur[RPW];
    #pragma unroll
    for (int a = 0; a < RPW; a++)
        cur[a] = __ldcs(&x2[(size_t)(row0 + a) * D4 + kb4 + lane]);

    #pragma unroll 1
    for (int kt = 0; kt < NKT - 1; kt++) {
        // prefetch tile kt+1 (in flight during this tile's FMAs)
        ulonglong2 nxt[RPW];
        const int i4n = kb4 + (kt + 1) * 32 + lane;
        #pragma unroll
        for (int a = 0; a < RPW; a++)
            nxt[a] = __ldcs(&x2[(size_t)(row0 + a) * D4 + i4n]);

        // compute tile kt
        const int i4 = kb4 + kt * 32 + lane;
        #pragma unroll
        for (int r = 0; r < R_DIM; r++) {
            const ulonglong2 bv = B2[r * D4 + i4];          // L1/L2-hot
            #pragma unroll
            for (int a = 0; a < RPW; a++) {
                fma_f32x2(acc2[a][r], cur[a].x, bv.x);
                fma_f32x2(acc2[a][r], cur[a].y, bv.y);
            }
        }
        #pragma unroll
        for (int a = 0; a < RPW; a++) cur[a] = nxt[a];
    }

    // epilogue: compute last tile
    {
        const int i4 = kb4 + (NKT - 1) * 32 + lane;
        #pragma unroll
        for (int r = 0; r < R_DIM; r++) {
            const ulonglong2 bv = B2[r * D4 + i4];
            #pragma unroll
            for (int a = 0; a < RPW; a++) {
                fma_f32x2(acc2[a][r], cur[a].x, bv.x);
                fma_f32x2(acc2[a][r], cur[a].y, bv.y);
            }
        }
    }

    // Unpack f32x2 accumulators (lo+hi), then butterfly-reduce across lanes.
    float acc[RPW][R_DIM];
    #pragma unroll
    for (int a = 0; a < RPW; a++)
        #pragma unroll
        for (int r = 0; r < R_DIM; r++) {
            float lo, hi;
            asm("mov.b64 {%0, %1}, %2;" : "=f"(lo), "=f"(hi) : "l"(acc2[a][r]));
            acc[a][r] = lo + hi;
        }

    #pragma unroll
    for (int a = 0; a < RPW; a++)
        #pragma unroll
        for (int r = 0; r < R_DIM; r++)
            #pragma unroll
            for (int off = 16; off > 0; off >>= 1)
                acc[a][r] += __shfl_xor_sync(0xFFFFFFFFu, acc[a][r], off);

    const int a = lane >> 3;
    const int r = lane & 7;
    g_tp[kq][(size_t)(row0 + a) * R_DIM + r] = acc[a][r];
}

// ======================= Phase 2: out[n,d] = base[n,d] + sum_r t[n,r]*A[d,r] =
// Same R7 structure, but the 4-row base-load batches are software-pipelined:
// chunk c+1's loads issue before chunk c's FMAs/stores -> 8 loads in flight.
#define P2_THREADS 256
#define NT2 32                // rows per block
#define DT4 256               // float4 columns per block

__global__ __launch_bounds__(P2_THREADS)
void phase2_kernel(const float* __restrict__ base,
                   const float* __restrict__ A,
                   const float* __restrict__ P,
                   const float* __restrict__ v,
                   float* __restrict__ out)
{
    __shared__ float ts[NT2][R_DIM];          // 1 KB

    const int tid  = threadIdx.x;
    const int row0 = blockIdx.x * NT2;
    const int d4   = blockIdx.y * DT4 + tid;

    const float4* __restrict__ A4    = reinterpret_cast<const float4*>(A);
    const float4* __restrict__ base4 = reinterpret_cast<const float4*>(base);
    float4* __restrict__ out4        = reinterpret_cast<float4*>(out);

    // Fold split-k partials + scale: thread owns one (m, r).
    {
        const int m = tid >> 3, r = tid & 7;
        const size_t idx = (size_t)(row0 + m) * R_DIM + r;
        float s = 0.f;
        #pragma unroll
        for (int q = 0; q < SPLITK; q++) s += g_tp[q][idx];
        float sc = 0.f;
        #pragma unroll
        for (int u = 0; u < U_DIM; u++) sc += P[r * U_DIM + u] * v[u];
        ts[m][r] = s * sc;
    }

    // A rows for this thread's 4 consecutive d's.
    float4 a[8];
    #pragma unroll
    for (int j = 0; j < 8; j++)
        a[j] = A4[(size_t)d4 * 8 + j];

    __syncthreads();

    // prologue: load chunk 0
    float4 bv[4];
    #pragma unroll
    for (int i = 0; i < 4; i++)
        bv[i] = __ldcs(&base4[(size_t)(row0 + i) * D4 + d4]);

    #pragma unroll 1
    for (int c = 0; c < NT2; c += 4) {
        // prefetch chunk c+4
        float4 nv[4];
        if (c + 4 < NT2) {
            #pragma unroll
            for (int i = 0; i < 4; i++)
                nv[i] = __ldcs(&base4[(size_t)(row0 + c + 4 + i) * D4 + d4]);
        }

        #pragma unroll
        for (int i = 0; i < 4; i++) {
            const int mm = c + i;
            const float t0 = ts[mm][0], t1 = ts[mm][1], t2 = ts[mm][2], t3 = ts[mm][3];
            const float t4 = ts[mm][4], t5 = ts[mm][5], t6 = ts[mm][6], t7 = ts[mm][7];
            float4 o;
            o.x = bv[i].x + t0*a[0].x + t1*a[0].y + t2*a[0].z + t3*a[0].w
                          + t4*a[1].x + t5*a[1].y + t6*a[1].z + t7*a[1].w;
            o.y = bv[i].y + t0*a[2].x + t1*a[2].y + t2*a[2].z + t3*a[2].w
                          + t4*a[3].x + t5*a[3].y + t6*a[3].z + t7*a[3].w;
            o.z = bv[i].z + t0*a[4].x + t1*a[4].y + t2*a[4].z + t3*a[4].w
                          + t4*a[5].x + t5*a[5].y + t6*a[5].z + t7*a[5].w;
            o.w = bv[i].w + t0*a[6].x + t1*a[6].y + t2*a[6].z + t3*a[6].w
                          + t4*a[7].x + t5*a[7].y + t6*a[7].z + t7*a[7].w;
            __stcs(&out4[(size_t)(row0 + mm) * D4 + d4], o);
        }
        #pragma unroll
        for (int i = 0; i < 4; i++) bv[i] = nv[i];
    }
}

extern "C" void kernel_launch(void* const* d_in, const int* in_sizes, int n_in,
                              void* d_out, int out_size)
{
    const float* x    = (const float*)d_in[0];
    const float* base = (const float*)d_in[1];
    const float* A    = (const float*)d_in[2];
    const float* B    = (const float*)d_in[3];
    const float* P    = (const float*)d_in[4];
    const float* v    = (const float*)d_in[5];
    float* out = (float*)d_out;

    dim3 g1(N_ROWS / P1_ROWS_PER_BLOCK, SPLITK);  // (256, 4) = 1024 blocks
    phase1_kernel<<<g1, P1_THREADS>>>(x, B);

    dim3 g2(N_ROWS / NT2, D_DIM / (DT4 * 4));     // (256, 4) = 1024 blocks
    phase2_kernel<<<g2, P2_THREADS>>>(base, A, P, v, out);
}

// round 11
// speedup vs baseline: 1.0160x; 1.0160x over previous
#include <cuda_runtime.h>

// Problem constants (fixed: B_SZ=2, SEQ=4096, D=4096, R=8, U=4)
#define D_DIM  4096
#define D4     1024          // float4 per row
#define R_DIM  8
#define U_DIM  4
#define N_ROWS 8192

#define SPLITK 4
#define KQ4    (D4 / SPLITK) // 256 float4 per k-slice
#define NKT    (KQ4 / 32)    // 8 k-tiles per slice

// Split-k partials for t: 4 x 8192 x 8 floats = 1 MB (static, allowed).
__device__ float g_tp[SPLITK][N_ROWS * R_DIM];

// Packed f32x2 FMA: d = a*b + d (two fp32 lanes per instruction)
__device__ __forceinline__ void fma_f32x2(unsigned long long& d,
                                          unsigned long long a,
                                          unsigned long long b)
{
    asm("fma.rn.f32x2 %0, %1, %2, %0;" : "+l"(d) : "l"(a), "l"(b));
}

// ======================= Phase 1: partial t over one k-slice ================
// RPW=2: accumulators shrink 64->16 regs so occupancy doubles (4-5 blocks/SM,
// ~10 warps/SMSP) — enough warps to cover the ~380-cyc DRAM stall per tile,
// which R9/R10 could not (R10's prefetch blew registers instead; reverted).
// B's L1 traffic doubles vs RPW=4 but overlaps the DRAM stream on a
// different pipe. No prefetch, no smem, no barriers.
#define P1_THREADS 256
#define RPW 2                // rows per warp
#define P1_ROWS_PER_BLOCK (RPW * (P1_THREADS / 32))   // 16

__global__ __launch_bounds__(P1_THREADS)
void phase1_kernel(const float* __restrict__ x,
                   const float* __restrict__ B)
{
    const int tid  = threadIdx.x;
    const int w    = tid >> 5;
    const int lane = tid & 31;
    const int row0 = blockIdx.x * P1_ROWS_PER_BLOCK + w * RPW;
    const int kq   = blockIdx.y;
    const int kb4  = kq * KQ4;

    const ulonglong2* __restrict__ x2 = reinterpret_cast<const ulonglong2*>(x);
    const ulonglong2* __restrict__ B2 = reinterpret_cast<const ulonglong2*>(B);

    unsigned long long acc2[RPW][R_DIM];     // f32x2 accumulators (16 regs)
    #pragma unroll
    for (int a = 0; a < RPW; a++)
        #pragma unroll
        for (int r = 0; r < R_DIM; r++) acc2[a][r] = 0ull;

    #pragma unroll 2
    for (int kt = 0; kt < NKT; kt++) {            // 8 k-tiles of 32 float4
        const int i4 = kb4 + kt * 32 + lane;
        ulonglong2 xv[RPW];
        #pragma unroll
        for (int a = 0; a < RPW; a++)
            xv[a] = __ldcs(&x2[(size_t)(row0 + a) * D4 + i4]);   // stream
        #pragma unroll
        for (int r = 0; r < R_DIM; r++) {
            const ulonglong2 bv = B2[r * D4 + i4];               // L1/L2-hot
            #pragma unroll
            for (int a = 0; a < RPW; a++) {
                fma_f32x2(acc2[a][r], xv[a].x, bv.x);
                fma_f32x2(acc2[a][r], xv[a].y, bv.y);
            }
        }
    }

    // Unpack f32x2 accumulators (lo+hi), then butterfly-reduce across lanes.
    float acc[RPW][R_DIM];
    #pragma unroll
    for (int a = 0; a < RPW; a++)
        #pragma unroll
        for (int r = 0; r < R_DIM; r++) {
            float lo, hi;
            asm("mov.b64 {%0, %1}, %2;" : "=f"(lo), "=f"(hi) : "l"(acc2[a][r]));
            acc[a][r] = lo + hi;
        }

    #pragma unroll
    for (int a = 0; a < RPW; a++)
        #pragma unroll
        for (int r = 0; r < R_DIM; r++)
            #pragma unroll
            for (int off = 16; off > 0; off >>= 1)
                acc[a][r] += __shfl_xor_sync(0xFFFFFFFFu, acc[a][r], off);

    // Lanes 0..15 write (a = l>>3, r = l&7): 64B coalesced per warp.
    if (lane < RPW * R_DIM) {
        const int a = lane >> 3;
        const int r = lane & 7;
        g_tp[kq][(size_t)(row0 + a) * R_DIM + r] = acc[a][r];
    }
}

// ======================= Phase 2: out[n,d] = base[n,d] + sum_r t[n,r]*A[d,r] =
// R10 form (best measured): fold 4 split-k partials + scale into t-tile;
// thread pins its 4 columns' A rows; 4-row base-load chunks software-
// pipelined; .cs on the zero-reuse streams.
#define P2_THREADS 256
#define NT2 32                // rows per block
#define DT4 256               // float4 columns per block

__global__ __launch_bounds__(P2_THREADS)
void phase2_kernel(const float* __restrict__ base,
                   const float* __restrict__ A,
                   const float* __restrict__ P,
                   const float* __restrict__ v,
                   float* __restrict__ out)
{
    __shared__ float ts[NT2][R_DIM];          // 1 KB

    const int tid  = threadIdx.x;
    const int row0 = blockIdx.x * NT2;
    const int d4   = blockIdx.y * DT4 + tid;

    const float4* __restrict__ A4    = reinterpret_cast<const float4*>(A);
    const float4* __restrict__ base4 = reinterpret_cast<const float4*>(base);
    float4* __restrict__ out4        = reinterpret_cast<float4*>(out);

    // Fold split-k partials + scale: thread owns one (m, r).
    {
        const int m = tid >> 3, r = tid & 7;
        const size_t idx = (size_t)(row0 + m) * R_DIM + r;
        float s = 0.f;
        #pragma unroll
        for (int q = 0; q < SPLITK; q++) s += g_tp[q][idx];
        float sc = 0.f;
        #pragma unroll
        for (int u = 0; u < U_DIM; u++) sc += P[r * U_DIM + u] * v[u];
        ts[m][r] = s * sc;
    }

    // A rows for this thread's 4 consecutive d's.
    float4 a[8];
    #pragma unroll
    for (int j = 0; j < 8; j++)
        a[j] = A4[(size_t)d4 * 8 + j];

    __syncthreads();

    // prologue: load chunk 0
    float4 bv[4];
    #pragma unroll
    for (int i = 0; i < 4; i++)
        bv[i] = __ldcs(&base4[(size_t)(row0 + i) * D4 + d4]);

    #pragma unroll 1
    for (int c = 0; c < NT2; c += 4) {
        // prefetch chunk c+4
        float4 nv[4];
        if (c + 4 < NT2) {
            #pragma unroll
            for (int i = 0; i < 4; i++)
                nv[i] = __ldcs(&base4[(size_t)(row0 + c + 4 + i) * D4 + d4]);
        }

        #pragma unroll
        for (int i = 0; i < 4; i++) {
            const int mm = c + i;
            const float t0 = ts[mm][0], t1 = ts[mm][1], t2 = ts[mm][2], t3 = ts[mm][3];
            const float t4 = ts[mm][4], t5 = ts[mm][5], t6 = ts[mm][6], t7 = ts[mm][7];
            float4 o;
            o.x = bv[i].x + t0*a[0].x + t1*a[0].y + t2*a[0].z + t3*a[0].w
                          + t4*a[1].x + t5*a[1].y + t6*a[1].z + t7*a[1].w;
            o.y = bv[i].y + t0*a[2].x + t1*a[2].y + t2*a[2].z + t3*a[2].w
                          + t4*a[3].x + t5*a[3].y + t6*a[3].z + t7*a[3].w;
            o.z = bv[i].z + t0*a[4].x + t1*a[4].y + t2*a[4].z + t3*a[4].w
                          + t4*a[5].x + t5*a[5].y + t6*a[5].z + t7*a[5].w;
            o.w = bv[i].w + t0*a[6].x + t1*a[6].y + t2*a[6].z + t3*a[6].w
                          + t4*a[7].x + t5*a[7].y + t6*a[7].z + t7*a[7].w;
            __stcs(&out4[(size_t)(row0 + mm) * D4 + d4], o);
        }
        #pragma unroll
        for (int i = 0; i < 4; i++) bv[i] = nv[i];
    }
}

extern "C" void kernel_launch(void* const* d_in, const int* in_sizes, int n_in,
                              void* d_out, int out_size)
{
    const float* x    = (const float*)d_in[0];
    const float* base = (const float*)d_in[1];
    const float* A    = (const float*)d_in[2];
    const float* B    = (const float*)d_in[3];
    const float* P    = (const float*)d_in[4];
    const float* v    = (const float*)d_in[5];
    float* out = (float*)d_out;

    dim3 g1(N_ROWS / P1_ROWS_PER_BLOCK, SPLITK);  // (512, 4) = 2048 blocks
    phase1_kernel<<<g1, P1_THREADS>>>(x, B);

    dim3 g2(N_ROWS / NT2, D_DIM / (DT4 * 4));     // (256, 4) = 1024 blocks
    phase2_kernel<<<g2, P2_THREADS>>>(base, A, P, v, out);
}